// round 1
// baseline (speedup 1.0000x reference)
#include <cuda_runtime.h>
#include <cstdint>
#include <math_constants.h>

#define BATCH 4
#define S_LEN 4096
#define EMB   1024
#define HD    64
#define M_ROWS (BATCH * S_LEN)   // 16384

// ---------------- scratch (no allocs allowed) ----------------
__device__ float g_q[M_ROWS * HD];
__device__ float g_k[M_ROWS * HD];
__device__ float g_v[M_ROWS * HD];

// ---------------- helpers ----------------
__device__ __forceinline__ uint32_t f2tf32(float f) {
    uint32_t u;
    asm("cvt.rna.tf32.f32 %0, %1;" : "=r"(u) : "f"(f));
    return u;
}

__device__ __forceinline__ void mma_tf32(float c[4], const uint32_t a[4], const uint32_t b[2]) {
    asm volatile(
        "mma.sync.aligned.m16n8k8.row.col.f32.tf32.tf32.f32 "
        "{%0,%1,%2,%3}, {%4,%5,%6,%7}, {%8,%9}, {%0,%1,%2,%3};"
        : "+f"(c[0]), "+f"(c[1]), "+f"(c[2]), "+f"(c[3])
        : "r"(a[0]), "r"(a[1]), "r"(a[2]), "r"(a[3]), "r"(b[0]), "r"(b[1]));
}

// =====================================================================
// Kernel 1: fused QKV projection.
//   q/k/v[m,d] = sum_e x[m,e] * W{q,k,v}[d,e]
// Block: 128 rows x 192 cols (Wq|Wk|Wv concatenated), 256 threads (8 warps).
// Each warp owns 16 rows x 192 cols. K-chunks of 32.
// =====================================================================
#define PK_ROWS 128
#define PK_KC   32
#define XS_STR  36   // pad: bank (4g+r) distinct; multiple of 4 for float4 stores
#define WS_STR  36

__global__ __launch_bounds__(256, 1)
void qkv_proj_kernel(const float* __restrict__ x,
                     const float* __restrict__ Wq,
                     const float* __restrict__ Wk,
                     const float* __restrict__ Wv)
{
    __shared__ float Xs[PK_ROWS * XS_STR];
    __shared__ float Ws[192 * WS_STR];

    const int tid  = threadIdx.x;
    const int warp = tid >> 5;
    const int lane = tid & 31;
    const int g    = lane >> 2;   // groupID
    const int r    = lane & 3;    // threadID in group
    const int m0   = blockIdx.x * PK_ROWS;

    float acc[24][4];
#pragma unroll
    for (int j = 0; j < 24; j++)
#pragma unroll
        for (int i = 0; i < 4; i++) acc[j][i] = 0.f;

    for (int kc = 0; kc < EMB; kc += PK_KC) {
        // ---- load X tile 128x32 (1024 float4), convert to tf32 bits ----
#pragma unroll
        for (int i = 0; i < 4; i++) {
            int idx = tid + i * 256;
            int row = idx >> 3;
            int c4  = (idx & 7) << 2;
            float4 v = *(const float4*)&x[(size_t)(m0 + row) * EMB + kc + c4];
            float* d = &Xs[row * XS_STR + c4];
            d[0] = __uint_as_float(f2tf32(v.x));
            d[1] = __uint_as_float(f2tf32(v.y));
            d[2] = __uint_as_float(f2tf32(v.z));
            d[3] = __uint_as_float(f2tf32(v.w));
        }
        // ---- load W tile 192x32 (1536 float4) ----
#pragma unroll
        for (int i = 0; i < 6; i++) {
            int idx = tid + i * 256;
            int row = idx >> 3;
            int c4  = (idx & 7) << 2;
            const float* Wm = (row < 64) ? Wq : ((row < 128) ? Wk : Wv);
            int wr = row & 63;
            float4 v = *(const float4*)&Wm[(size_t)wr * EMB + kc + c4];
            float* d = &Ws[row * WS_STR + c4];
            d[0] = __uint_as_float(f2tf32(v.x));
            d[1] = __uint_as_float(f2tf32(v.y));
            d[2] = __uint_as_float(f2tf32(v.z));
            d[3] = __uint_as_float(f2tf32(v.w));
        }
        __syncthreads();

        const int row0 = warp * 16 + g;
#pragma unroll
        for (int kk = 0; kk < 4; kk++) {
            uint32_t a[4];
            a[0] = __float_as_uint(Xs[row0 * XS_STR + kk * 8 + r]);
            a[1] = __float_as_uint(Xs[(row0 + 8) * XS_STR + kk * 8 + r]);
            a[2] = __float_as_uint(Xs[row0 * XS_STR + kk * 8 + r + 4]);
            a[3] = __float_as_uint(Xs[(row0 + 8) * XS_STR + kk * 8 + r + 4]);
#pragma unroll
            for (int j = 0; j < 24; j++) {
                uint32_t b[2];
                int wrow = j * 8 + (lane >> 2);
                b[0] = __float_as_uint(Ws[wrow * WS_STR + kk * 8 + r]);
                b[1] = __float_as_uint(Ws[wrow * WS_STR + kk * 8 + r + 4]);
                mma_tf32(acc[j], a, b);
            }
        }
        __syncthreads();
    }

    // ---- epilogue: scatter to q/k/v scratch ----
    const int row0 = m0 + warp * 16 + g;
#pragma unroll
    for (int j = 0; j < 24; j++) {
        float* o = (j < 8) ? g_q : ((j < 16) ? g_k : g_v);
        int col = (j & 7) * 8 + 2 * r;
        o[(size_t)row0 * HD + col]           = acc[j][0];
        o[(size_t)row0 * HD + col + 1]       = acc[j][1];
        o[(size_t)(row0 + 8) * HD + col]     = acc[j][2];
        o[(size_t)(row0 + 8) * HD + col + 1] = acc[j][3];
    }
}

// =====================================================================
// Kernel 2: flash attention (tf32 mma, fp32 accumulate, online softmax).
// Block: 128 q rows, 256 threads (8 warps, each 16 q rows).
// KV tiles of 64 keys, 64 iterations over S=4096.
// =====================================================================
#define KV_TILE 64
#define KV_STR  68   // pad: bank (4c+r) distinct; multiple of 4

__global__ __launch_bounds__(256, 1)
void flash_attn_kernel(float* __restrict__ out)
{
    __shared__ float Ksm[KV_TILE * KV_STR];
    __shared__ float Vsm[KV_TILE * KV_STR];

    const int tid  = threadIdx.x;
    const int warp = tid >> 5;
    const int lane = tid & 31;
    const int g    = lane >> 2;
    const int r    = lane & 3;

    const int b  = blockIdx.y;
    const int q0 = blockIdx.x * 128;

    const float* qb = g_q + ((size_t)b * S_LEN + q0) * HD;
    const float* kb = g_k + (size_t)b * S_LEN * HD;
    const float* vb = g_v + (size_t)b * S_LEN * HD;

    // ---- stage Q tile (128x64) into Ksm(rows 0..63) + Vsm(rows 64..127) ----
#pragma unroll
    for (int i = 0; i < 8; i++) {
        int idx = tid + i * 256;         // 2048 float4
        int row = idx >> 4;
        int c4  = (idx & 15) << 2;
        float4 v = *(const float4*)&qb[(size_t)row * HD + c4];
        float* dstbuf = (row < 64) ? Ksm : Vsm;
        float* d = &dstbuf[(row & 63) * KV_STR + c4];
        d[0] = v.x; d[1] = v.y; d[2] = v.z; d[3] = v.w;
    }
    __syncthreads();

    // ---- Q fragments (scaled by 1/sqrt(64), converted to tf32) ----
    const int row0 = warp * 16 + g;
    uint32_t aq[8][4];
    {
        const float* qbuf = (warp < 4) ? Ksm : Vsm;
        int qr = row0 & 63;
#pragma unroll
        for (int kk = 0; kk < 8; kk++) {
            aq[kk][0] = f2tf32(0.125f * qbuf[qr * KV_STR + kk * 8 + r]);
            aq[kk][1] = f2tf32(0.125f * qbuf[(qr + 8) * KV_STR + kk * 8 + r]);
            aq[kk][2] = f2tf32(0.125f * qbuf[qr * KV_STR + kk * 8 + r + 4]);
            aq[kk][3] = f2tf32(0.125f * qbuf[(qr + 8) * KV_STR + kk * 8 + r + 4]);
        }
    }
    __syncthreads();

    float O[8][4];
#pragma unroll
    for (int j = 0; j < 8; j++)
#pragma unroll
        for (int i = 0; i < 4; i++) O[j][i] = 0.f;
    float m0v = -CUDART_INF_F, m1v = -CUDART_INF_F;
    float l0 = 0.f, l1 = 0.f;

    for (int t = 0; t < S_LEN / KV_TILE; t++) {
        const float* kt = kb + (size_t)t * KV_TILE * HD;
        const float* vt = vb + (size_t)t * KV_TILE * HD;

        // ---- load K,V tiles (64x64 each), tf32-convert at store ----
#pragma unroll
        for (int i = 0; i < 4; i++) {
            int idx = tid + i * 256;     // 1024 float4 per tensor
            int row = idx >> 4;
            int c4  = (idx & 15) << 2;
            float4 kv = *(const float4*)&kt[(size_t)row * HD + c4];
            float* dk = &Ksm[row * KV_STR + c4];
            dk[0] = __uint_as_float(f2tf32(kv.x));
            dk[1] = __uint_as_float(f2tf32(kv.y));
            dk[2] = __uint_as_float(f2tf32(kv.z));
            dk[3] = __uint_as_float(f2tf32(kv.w));
            float4 vv = *(const float4*)&vt[(size_t)row * HD + c4];
            float* dv = &Vsm[row * KV_STR + c4];
            dv[0] = __uint_as_float(f2tf32(vv.x));
            dv[1] = __uint_as_float(f2tf32(vv.y));
            dv[2] = __uint_as_float(f2tf32(vv.z));
            dv[3] = __uint_as_float(f2tf32(vv.w));
        }
        __syncthreads();

        // ---- S = (Q/8) @ K^T : 16x64 per warp ----
        float sacc[8][4];
#pragma unroll
        for (int j = 0; j < 8; j++)
#pragma unroll
            for (int i = 0; i < 4; i++) sacc[j][i] = 0.f;

#pragma unroll
        for (int kk = 0; kk < 8; kk++) {
#pragma unroll
            for (int j = 0; j < 8; j++) {
                uint32_t bfr[2];
                int krow = j * 8 + (lane >> 2);
                bfr[0] = __float_as_uint(Ksm[krow * KV_STR + kk * 8 + r]);
                bfr[1] = __float_as_uint(Ksm[krow * KV_STR + kk * 8 + r + 4]);
                mma_tf32(sacc[j], aq[kk], bfr);
            }
        }

        // ---- online softmax (rows g and g+8) ----
        float mx0 = -CUDART_INF_F, mx1 = -CUDART_INF_F;
#pragma unroll
        for (int j = 0; j < 8; j++) {
            mx0 = fmaxf(mx0, fmaxf(sacc[j][0], sacc[j][1]));
            mx1 = fmaxf(mx1, fmaxf(sacc[j][2], sacc[j][3]));
        }
        mx0 = fmaxf(mx0, __shfl_xor_sync(0xffffffffu, mx0, 1));
        mx0 = fmaxf(mx0, __shfl_xor_sync(0xffffffffu, mx0, 2));
        mx1 = fmaxf(mx1, __shfl_xor_sync(0xffffffffu, mx1, 1));
        mx1 = fmaxf(mx1, __shfl_xor_sync(0xffffffffu, mx1, 2));

        float mn0 = fmaxf(m0v, mx0);
        float mn1 = fmaxf(m1v, mx1);
        float corr0 = __expf(m0v - mn0);
        float corr1 = __expf(m1v - mn1);

        float rs0 = 0.f, rs1 = 0.f;
#pragma unroll
        for (int j = 0; j < 8; j++) {
            float p0 = __expf(sacc[j][0] - mn0);
            float p1 = __expf(sacc[j][1] - mn0);
            float p2 = __expf(sacc[j][2] - mn1);
            float p3 = __expf(sacc[j][3] - mn1);
            rs0 += p0 + p1;
            rs1 += p2 + p3;
            sacc[j][0] = __uint_as_float(f2tf32(p0));
            sacc[j][1] = __uint_as_float(f2tf32(p1));
            sacc[j][2] = __uint_as_float(f2tf32(p2));
            sacc[j][3] = __uint_as_float(f2tf32(p3));
        }
        rs0 += __shfl_xor_sync(0xffffffffu, rs0, 1);
        rs0 += __shfl_xor_sync(0xffffffffu, rs0, 2);
        rs1 += __shfl_xor_sync(0xffffffffu, rs1, 1);
        rs1 += __shfl_xor_sync(0xffffffffu, rs1, 2);

        l0 = l0 * corr0 + rs0;
        l1 = l1 * corr1 + rs1;
        m0v = mn0;
        m1v = mn1;

#pragma unroll
        for (int j = 0; j < 8; j++) {
            O[j][0] *= corr0; O[j][1] *= corr0;
            O[j][2] *= corr1; O[j][3] *= corr1;
        }

        // ---- O += P @ V ; P A-fragments via intra-quad shuffles ----
#pragma unroll
        for (int kk = 0; kk < 8; kk++) {
            float c0 = sacc[kk][0], c1 = sacc[kk][1];
            float c2 = sacc[kk][2], c3 = sacc[kk][3];
            int src0 = r >> 1;
            int src1 = (r >> 1) + 2;
            float x0 = __shfl_sync(0xffffffffu, c0, src0, 4);
            float x1 = __shfl_sync(0xffffffffu, c1, src0, 4);
            float y0 = __shfl_sync(0xffffffffu, c0, src1, 4);
            float y1 = __shfl_sync(0xffffffffu, c1, src1, 4);
            float z0 = __shfl_sync(0xffffffffu, c2, src0, 4);
            float z1 = __shfl_sync(0xffffffffu, c3, src0, 4);
            float w0 = __shfl_sync(0xffffffffu, c2, src1, 4);
            float w1 = __shfl_sync(0xffffffffu, c3, src1, 4);
            uint32_t a[4];
            a[0] = __float_as_uint((r & 1) ? x1 : x0);  // P[g   ][8kk+r]
            a[1] = __float_as_uint((r & 1) ? z1 : z0);  // P[g+8 ][8kk+r]
            a[2] = __float_as_uint((r & 1) ? y1 : y0);  // P[g   ][8kk+r+4]
            a[3] = __float_as_uint((r & 1) ? w1 : w0);  // P[g+8 ][8kk+r+4]
#pragma unroll
            for (int j = 0; j < 8; j++) {
                uint32_t bfr[2];
                int vrow = kk * 8 + r;
                bfr[0] = __float_as_uint(Vsm[vrow * KV_STR + j * 8 + (lane >> 2)]);
                bfr[1] = __float_as_uint(Vsm[(vrow + 4) * KV_STR + j * 8 + (lane >> 2)]);
                mma_tf32(O[j], a, bfr);
            }
        }
        __syncthreads();
    }

    // ---- epilogue: O / l -> out ----
    float inv0 = 1.f / l0;
    float inv1 = 1.f / l1;
    float* ob = out + ((size_t)b * S_LEN + q0) * HD;
#pragma unroll
    for (int j = 0; j < 8; j++) {
        int col = j * 8 + 2 * r;
        ob[(size_t)row0 * HD + col]           = O[j][0] * inv0;
        ob[(size_t)row0 * HD + col + 1]       = O[j][1] * inv0;
        ob[(size_t)(row0 + 8) * HD + col]     = O[j][2] * inv1;
        ob[(size_t)(row0 + 8) * HD + col + 1] = O[j][3] * inv1;
    }
}

// =====================================================================
extern "C" void kernel_launch(void* const* d_in, const int* in_sizes, int n_in,
                              void* d_out, int out_size)
{
    const float* x  = (const float*)d_in[0];
    const float* Wq = (const float*)d_in[1];
    const float* Wk = (const float*)d_in[2];
    const float* Wv = (const float*)d_in[3];
    float* out = (float*)d_out;

    qkv_proj_kernel<<<M_ROWS / PK_ROWS, 256>>>(x, Wq, Wk, Wv);

    dim3 grid(S_LEN / 128, BATCH);
    flash_attn_kernel<<<grid, 256>>>(out);
}

// round 3
// speedup vs baseline: 1.1155x; 1.1155x over previous
#include <cuda_runtime.h>
#include <cstdint>
#include <math_constants.h>

#define BATCH 4
#define S_LEN 4096
#define EMB   1024
#define HD    64
#define M_ROWS (BATCH * S_LEN)   // 16384

// ---------------- scratch (no allocs allowed) ----------------
__device__ float g_q[M_ROWS * HD];
__device__ float g_k[M_ROWS * HD];
__device__ float g_v[M_ROWS * HD];

// ---------------- helpers ----------------
__device__ __forceinline__ uint32_t f2tf32(float f) {
    uint32_t u;
    asm("cvt.rna.tf32.f32 %0, %1;" : "=r"(u) : "f"(f));
    return u;
}

__device__ __forceinline__ void mma_tf32(float c[4], const uint32_t a[4], const uint32_t b[2]) {
    asm volatile(
        "mma.sync.aligned.m16n8k8.row.col.f32.tf32.tf32.f32 "
        "{%0,%1,%2,%3}, {%4,%5,%6,%7}, {%8,%9}, {%0,%1,%2,%3};"
        : "+f"(c[0]), "+f"(c[1]), "+f"(c[2]), "+f"(c[3])
        : "r"(a[0]), "r"(a[1]), "r"(a[2]), "r"(a[3]), "r"(b[0]), "r"(b[1]));
}

// Build P A-fragment (rows g,g+8; cols 8kk+r, 8kk+r+4) from C-fragment via
// intra-quad shuffles. Verified in round 1.
__device__ __forceinline__ void p_afrag(const float c[4], int r, uint32_t a[4]) {
    int src0 = r >> 1;
    int src1 = src0 + 2;
    float x0 = __shfl_sync(0xffffffffu, c[0], src0, 4);
    float x1 = __shfl_sync(0xffffffffu, c[1], src0, 4);
    float y0 = __shfl_sync(0xffffffffu, c[0], src1, 4);
    float y1 = __shfl_sync(0xffffffffu, c[1], src1, 4);
    float z0 = __shfl_sync(0xffffffffu, c[2], src0, 4);
    float z1 = __shfl_sync(0xffffffffu, c[3], src0, 4);
    float w0 = __shfl_sync(0xffffffffu, c[2], src1, 4);
    float w1 = __shfl_sync(0xffffffffu, c[3], src1, 4);
    a[0] = __float_as_uint((r & 1) ? x1 : x0);
    a[1] = __float_as_uint((r & 1) ? z1 : z0);
    a[2] = __float_as_uint((r & 1) ? y1 : y0);
    a[3] = __float_as_uint((r & 1) ? w1 : w0);
}

// =====================================================================
// Kernel 1: fused QKV projection (v2: 2x M reuse of B fragments).
// 256 threads / 8 warps. warps 0-3: col tiles 0..11, warps 4-7: 12..23.
// Each warp: 32 rows (two m16 halves sharing each B-fragment load).
// =====================================================================
#define XS_STR  36
#define WS_STR  36

__global__ __launch_bounds__(256, 1)
void qkv_proj_kernel(const float* __restrict__ x,
                     const float* __restrict__ Wq,
                     const float* __restrict__ Wk,
                     const float* __restrict__ Wv)
{
    __shared__ float Xs[128 * XS_STR];
    __shared__ float Ws[192 * WS_STR];

    const int tid   = threadIdx.x;
    const int warp  = tid >> 5;
    const int lane  = tid & 31;
    const int g     = lane >> 2;
    const int r     = lane & 3;
    const int jgrp  = warp >> 2;   // 0/1: which 12 col-tiles
    const int warpq = warp & 3;    // row group (32 rows)
    const int m0    = blockIdx.x * 128;

    float acc[2][12][4];
#pragma unroll
    for (int h = 0; h < 2; h++)
#pragma unroll
        for (int j = 0; j < 12; j++)
#pragma unroll
            for (int i = 0; i < 4; i++) acc[h][j][i] = 0.f;

    for (int kc = 0; kc < EMB; kc += 32) {
#pragma unroll
        for (int i = 0; i < 4; i++) {
            int idx = tid + i * 256;
            int row = idx >> 3;
            int c4  = (idx & 7) << 2;
            float4 v = *(const float4*)&x[(size_t)(m0 + row) * EMB + kc + c4];
            float* d = &Xs[row * XS_STR + c4];
            d[0] = __uint_as_float(f2tf32(v.x));
            d[1] = __uint_as_float(f2tf32(v.y));
            d[2] = __uint_as_float(f2tf32(v.z));
            d[3] = __uint_as_float(f2tf32(v.w));
        }
#pragma unroll
        for (int i = 0; i < 6; i++) {
            int idx = tid + i * 256;
            int row = idx >> 3;
            int c4  = (idx & 7) << 2;
            const float* Wm = (row < 64) ? Wq : ((row < 128) ? Wk : Wv);
            int wr = row & 63;
            float4 v = *(const float4*)&Wm[(size_t)wr * EMB + kc + c4];
            float* d = &Ws[row * WS_STR + c4];
            d[0] = __uint_as_float(f2tf32(v.x));
            d[1] = __uint_as_float(f2tf32(v.y));
            d[2] = __uint_as_float(f2tf32(v.z));
            d[3] = __uint_as_float(f2tf32(v.w));
        }
        __syncthreads();

#pragma unroll
        for (int kk = 0; kk < 4; kk++) {
            uint32_t a[2][4];
#pragma unroll
            for (int h = 0; h < 2; h++) {
                int row = warpq * 32 + h * 16 + g;
                a[h][0] = __float_as_uint(Xs[row * XS_STR + kk * 8 + r]);
                a[h][1] = __float_as_uint(Xs[(row + 8) * XS_STR + kk * 8 + r]);
                a[h][2] = __float_as_uint(Xs[row * XS_STR + kk * 8 + r + 4]);
                a[h][3] = __float_as_uint(Xs[(row + 8) * XS_STR + kk * 8 + r + 4]);
            }
#pragma unroll
            for (int j = 0; j < 12; j++) {
                uint32_t b[2];
                int wrow = (jgrp * 12 + j) * 8 + g;
                b[0] = __float_as_uint(Ws[wrow * WS_STR + kk * 8 + r]);
                b[1] = __float_as_uint(Ws[wrow * WS_STR + kk * 8 + r + 4]);
                mma_tf32(acc[0][j], a[0], b);
                mma_tf32(acc[1][j], a[1], b);
            }
        }
        __syncthreads();
    }

#pragma unroll
    for (int h = 0; h < 2; h++) {
        const int row0 = m0 + warpq * 32 + h * 16 + g;
#pragma unroll
        for (int j = 0; j < 12; j++) {
            int jj = jgrp * 12 + j;
            float* o = (jj < 8) ? g_q : ((jj < 16) ? g_k : g_v);
            int col = (jj & 7) * 8 + 2 * r;
            o[(size_t)row0 * HD + col]           = acc[h][j][0];
            o[(size_t)row0 * HD + col + 1]       = acc[h][j][1];
            o[(size_t)(row0 + 8) * HD + col]     = acc[h][j][2];
            o[(size_t)(row0 + 8) * HD + col + 1] = acc[h][j][3];
        }
    }
}

// =====================================================================
// Kernel 2: flash attention v2.
// 256 threads / 8 warps. KV tile per iter: 128 keys staged in smem.
//   warps 0-3 (kvh=0): keys [0,64) of the tile; warps 4-7: keys [64,128).
//   warp handles 32 q-rows (warpq*32), two m16 halves share B fragments.
// Split-KV partials (m,l,O) combined through smem at the end.
// =====================================================================
#define KV_STR 68
#define FSM_FLOATS (2 * 128 * KV_STR)
#define FSM_BYTES  (FSM_FLOATS * 4)

extern __shared__ float fsm[];

__global__ __launch_bounds__(256, 1)
void flash_attn_kernel(float* __restrict__ out)
{
    float* Ksm = fsm;
    float* Vsm = fsm + 128 * KV_STR;

    const int tid   = threadIdx.x;
    const int warp  = tid >> 5;
    const int lane  = tid & 31;
    const int g     = lane >> 2;
    const int r     = lane & 3;
    const int kvh   = warp >> 2;   // KV split group
    const int warpq = warp & 3;    // 32 q rows

    const int b  = blockIdx.y;
    const int q0 = blockIdx.x * 128;

    const float* qb = g_q + ((size_t)b * S_LEN + q0) * HD;
    const float* kb = g_k + (size_t)b * S_LEN * HD;
    const float* vb = g_v + (size_t)b * S_LEN * HD;

    // ---- stage Q tile (128x64) into Ksm rows 0..127 ----
#pragma unroll
    for (int i = 0; i < 8; i++) {
        int idx = tid + i * 256;       // 2048 float4
        int row = idx >> 4;
        int c4  = (idx & 15) << 2;
        float4 v = *(const float4*)&qb[(size_t)row * HD + c4];
        float* d = &Ksm[row * KV_STR + c4];
        d[0] = v.x; d[1] = v.y; d[2] = v.z; d[3] = v.w;
    }
    __syncthreads();

    // ---- Q fragments (scaled, tf32) for both halves ----
    uint32_t aq[2][8][4];
#pragma unroll
    for (int h = 0; h < 2; h++) {
        int qr = warpq * 32 + h * 16 + g;
#pragma unroll
        for (int kk = 0; kk < 8; kk++) {
            aq[h][kk][0] = f2tf32(0.125f * Ksm[qr * KV_STR + kk * 8 + r]);
            aq[h][kk][1] = f2tf32(0.125f * Ksm[(qr + 8) * KV_STR + kk * 8 + r]);
            aq[h][kk][2] = f2tf32(0.125f * Ksm[qr * KV_STR + kk * 8 + r + 4]);
            aq[h][kk][3] = f2tf32(0.125f * Ksm[(qr + 8) * KV_STR + kk * 8 + r + 4]);
        }
    }
    __syncthreads();

    float O[2][8][4];
#pragma unroll
    for (int h = 0; h < 2; h++)
#pragma unroll
        for (int j = 0; j < 8; j++)
#pragma unroll
            for (int i = 0; i < 4; i++) O[h][j][i] = 0.f;
    float mrun[2][2] = {{-CUDART_INF_F, -CUDART_INF_F}, {-CUDART_INF_F, -CUDART_INF_F}};
    float lrun[2][2] = {{0.f, 0.f}, {0.f, 0.f}};

    const int ks = kvh * 64;   // this group's key offset within the tile

    for (int t = 0; t < S_LEN / 128; t++) {
        // ---- load K,V (128x64 each), tf32-convert at store ----
#pragma unroll
        for (int i = 0; i < 8; i++) {
            int idx = tid + i * 256;
            int row = idx >> 4;
            int c4  = (idx & 15) << 2;
            size_t goff = (size_t)(t * 128 + row) * HD + c4;
            float4 kv = *(const float4*)&kb[goff];
            float* dk = &Ksm[row * KV_STR + c4];
            dk[0] = __uint_as_float(f2tf32(kv.x));
            dk[1] = __uint_as_float(f2tf32(kv.y));
            dk[2] = __uint_as_float(f2tf32(kv.z));
            dk[3] = __uint_as_float(f2tf32(kv.w));
            float4 vv = *(const float4*)&vb[goff];
            float* dv = &Vsm[row * KV_STR + c4];
            dv[0] = __uint_as_float(f2tf32(vv.x));
            dv[1] = __uint_as_float(f2tf32(vv.y));
            dv[2] = __uint_as_float(f2tf32(vv.z));
            dv[3] = __uint_as_float(f2tf32(vv.w));
        }
        __syncthreads();

        // ---- S = Q @ K^T : 32x64 per warp, B fragments shared by halves ----
        float sacc[2][8][4];
#pragma unroll
        for (int h = 0; h < 2; h++)
#pragma unroll
            for (int j = 0; j < 8; j++)
#pragma unroll
                for (int i = 0; i < 4; i++) sacc[h][j][i] = 0.f;

#pragma unroll
        for (int kk = 0; kk < 8; kk++) {
#pragma unroll
            for (int j = 0; j < 8; j++) {
                uint32_t bfr[2];
                int krow = ks + j * 8 + g;
                bfr[0] = __float_as_uint(Ksm[krow * KV_STR + kk * 8 + r]);
                bfr[1] = __float_as_uint(Ksm[krow * KV_STR + kk * 8 + r + 4]);
                mma_tf32(sacc[0][j], aq[0][kk], bfr);
                mma_tf32(sacc[1][j], aq[1][kk], bfr);
            }
        }

        // ---- online softmax per half (P kept as raw fp32; mma truncates) ----
#pragma unroll
        for (int h = 0; h < 2; h++) {
            float mx0 = -CUDART_INF_F, mx1 = -CUDART_INF_F;
#pragma unroll
            for (int j = 0; j < 8; j++) {
                mx0 = fmaxf(mx0, fmaxf(sacc[h][j][0], sacc[h][j][1]));
                mx1 = fmaxf(mx1, fmaxf(sacc[h][j][2], sacc[h][j][3]));
            }
            mx0 = fmaxf(mx0, __shfl_xor_sync(0xffffffffu, mx0, 1));
            mx0 = fmaxf(mx0, __shfl_xor_sync(0xffffffffu, mx0, 2));
            mx1 = fmaxf(mx1, __shfl_xor_sync(0xffffffffu, mx1, 1));
            mx1 = fmaxf(mx1, __shfl_xor_sync(0xffffffffu, mx1, 2));

            float mn0 = fmaxf(mrun[h][0], mx0);
            float mn1 = fmaxf(mrun[h][1], mx1);
            float corr0 = __expf(mrun[h][0] - mn0);
            float corr1 = __expf(mrun[h][1] - mn1);

            float rs0 = 0.f, rs1 = 0.f;
#pragma unroll
            for (int j = 0; j < 8; j++) {
                float p0 = __expf(sacc[h][j][0] - mn0);
                float p1 = __expf(sacc[h][j][1] - mn0);
                float p2 = __expf(sacc[h][j][2] - mn1);
                float p3 = __expf(sacc[h][j][3] - mn1);
                rs0 += p0 + p1;
                rs1 += p2 + p3;
                sacc[h][j][0] = p0;
                sacc[h][j][1] = p1;
                sacc[h][j][2] = p2;
                sacc[h][j][3] = p3;
            }
            rs0 += __shfl_xor_sync(0xffffffffu, rs0, 1);
            rs0 += __shfl_xor_sync(0xffffffffu, rs0, 2);
            rs1 += __shfl_xor_sync(0xffffffffu, rs1, 1);
            rs1 += __shfl_xor_sync(0xffffffffu, rs1, 2);

            lrun[h][0] = lrun[h][0] * corr0 + rs0;
            lrun[h][1] = lrun[h][1] * corr1 + rs1;
            mrun[h][0] = mn0;
            mrun[h][1] = mn1;

#pragma unroll
            for (int j = 0; j < 8; j++) {
                O[h][j][0] *= corr0; O[h][j][1] *= corr0;
                O[h][j][2] *= corr1; O[h][j][3] *= corr1;
            }
        }

        // ---- O += P @ V ; V B-fragments shared by halves ----
#pragma unroll
        for (int kk = 0; kk < 8; kk++) {
            uint32_t aP0[4], aP1[4];
            p_afrag(sacc[0][kk], r, aP0);
            p_afrag(sacc[1][kk], r, aP1);
#pragma unroll
            for (int j = 0; j < 8; j++) {
                uint32_t bfr[2];
                int vrow = ks + kk * 8 + r;
                bfr[0] = __float_as_uint(Vsm[vrow * KV_STR + j * 8 + g]);
                bfr[1] = __float_as_uint(Vsm[(vrow + 4) * KV_STR + j * 8 + g]);
                mma_tf32(O[0][j], aP0, bfr);
                mma_tf32(O[1][j], aP1, bfr);
            }
        }
        __syncthreads();
    }

    // ---- split-KV combine through smem ----
    float* Osm = fsm;              // 128 x 68 (padded)
    float* Msm = fsm + 128 * KV_STR;
    float* Lsm = Msm + 128;

    if (kvh == 1) {
#pragma unroll
        for (int h = 0; h < 2; h++) {
            int r0 = warpq * 32 + h * 16 + g;
            if (r == 0) {
                Msm[r0]     = mrun[h][0];
                Lsm[r0]     = lrun[h][0];
                Msm[r0 + 8] = mrun[h][1];
                Lsm[r0 + 8] = lrun[h][1];
            }
#pragma unroll
            for (int j = 0; j < 8; j++) {
                int col = j * 8 + 2 * r;
                Osm[r0 * KV_STR + col]           = O[h][j][0];
                Osm[r0 * KV_STR + col + 1]       = O[h][j][1];
                Osm[(r0 + 8) * KV_STR + col]     = O[h][j][2];
                Osm[(r0 + 8) * KV_STR + col + 1] = O[h][j][3];
            }
        }
    }
    __syncthreads();

    if (kvh == 0) {
        float* ob = out + ((size_t)b * S_LEN + q0) * HD;
#pragma unroll
        for (int h = 0; h < 2; h++) {
            int r0 = warpq * 32 + h * 16 + g;
            float m1a = Msm[r0],     l1a = Lsm[r0];
            float m1b = Msm[r0 + 8], l1b = Lsm[r0 + 8];

            float mfa = fmaxf(mrun[h][0], m1a);
            float e0a = __expf(mrun[h][0] - mfa);
            float e1a = __expf(m1a - mfa);
            float inva = 1.f / (lrun[h][0] * e0a + l1a * e1a);

            float mfb = fmaxf(mrun[h][1], m1b);
            float e0b = __expf(mrun[h][1] - mfb);
            float e1b = __expf(m1b - mfb);
            float invb = 1.f / (lrun[h][1] * e0b + l1b * e1b);

#pragma unroll
            for (int j = 0; j < 8; j++) {
                int col = j * 8 + 2 * r;
                ob[(size_t)r0 * HD + col] =
                    (O[h][j][0] * e0a + Osm[r0 * KV_STR + col] * e1a) * inva;
                ob[(size_t)r0 * HD + col + 1] =
                    (O[h][j][1] * e0a + Osm[r0 * KV_STR + col + 1] * e1a) * inva;
                ob[(size_t)(r0 + 8) * HD + col] =
                    (O[h][j][2] * e0b + Osm[(r0 + 8) * KV_STR + col] * e1b) * invb;
                ob[(size_t)(r0 + 8) * HD + col + 1] =
                    (O[h][j][3] * e0b + Osm[(r0 + 8) * KV_STR + col + 1] * e1b) * invb;
            }
        }
    }
}

// =====================================================================
extern "C" void kernel_launch(void* const* d_in, const int* in_sizes, int n_in,
                              void* d_out, int out_size)
{
    const float* x  = (const float*)d_in[0];
    const float* Wq = (const float*)d_in[1];
    const float* Wk = (const float*)d_in[2];
    const float* Wv = (const float*)d_in[3];
    float* out = (float*)d_out;

    qkv_proj_kernel<<<M_ROWS / 128, 256>>>(x, Wq, Wk, Wv);

    cudaFuncSetAttribute(flash_attn_kernel,
                         cudaFuncAttributeMaxDynamicSharedMemorySize, FSM_BYTES);
    dim3 grid(S_LEN / 128, BATCH);
    flash_attn_kernel<<<grid, 256, FSM_BYTES>>>(out);
}